// round 11
// baseline (speedup 1.0000x reference)
#include <cuda_runtime.h>
#include <cuda_fp16.h>
#include <math.h>
#include <stdint.h>

#define CIN   64
#define COUT  128
#define HH    128
#define WW    128
#define NB    32

// ---------------- persistent scratch (__device__ globals) -------------------
// Activations: [n][h][pix(128)][ic(64)] fp16 (16KB per row tile)
__device__ uint4 g_x1[(size_t)NB * HH * 1024];
// Winograd-transformed weights: [pos(16)][oc(128)][ic(64)] fp16 (16KB per pos)
__device__ uint4 g_u[16 * 1024];

// ---------------- pre-pass: x -> fp16 transposed tiles ----------------------
__global__ void prep_x(const float* __restrict__ x) {
    __shared__ __half sh[128 * 72];
    const int h = blockIdx.x, n = blockIdx.y;
    const float* xb = x + (size_t)n * CIN * HH * WW;
#pragma unroll
    for (int i = 0; i < 8; i++) {
        int f = threadIdx.x + i * 256;      // 0..2047 = ic*32 + p4
        int ic = f >> 5, p4 = f & 31;
        float4 v = *(const float4*)(xb + ((size_t)ic * HH + h) * WW + p4 * 4);
        float vv[4] = {v.x, v.y, v.z, v.w};
#pragma unroll
        for (int j = 0; j < 4; j++)
            sh[(p4 * 4 + j) * 72 + ic] = __float2half_rn(vv[j]);
    }
    __syncthreads();
    uint4* dst = g_x1 + (size_t)(n * HH + h) * 1024;
    for (int q = threadIdx.x; q < 1024; q += 256) {
        int p = q >> 3, c = q & 7;
        dst[q] = *(const uint4*)((const char*)sh + p * 144 + c * 16);
    }
}

// ---------------- pre-pass: weights -> Winograd U (fp32-exact -> fp16) ------
__global__ void prep_uw(const float* __restrict__ w) {
    int idx = blockIdx.x * 256 + threadIdx.x;      // 0..8191 = oc*64+ic
    if (idx >= COUT * CIN) return;
    int oc = idx >> 6, ic = idx & 63;
    float g[3][3];
#pragma unroll
    for (int r = 0; r < 3; r++)
#pragma unroll
        for (int c = 0; c < 3; c++)
            g[r][c] = w[((size_t)(ic * COUT + oc) * 3 + (2 - r)) * 3 + (2 - c)];
    float t[4][3];
#pragma unroll
    for (int c = 0; c < 3; c++) {
        t[0][c] = g[0][c];
        t[1][c] = 0.5f * (g[0][c] + g[1][c] + g[2][c]);
        t[2][c] = 0.5f * (g[0][c] - g[1][c] + g[2][c]);
        t[3][c] = g[2][c];
    }
    __half* dst = (__half*)g_u;
#pragma unroll
    for (int r = 0; r < 4; r++) {
        float u0 = t[r][0];
        float u1 = 0.5f * (t[r][0] + t[r][1] + t[r][2]);
        float u2 = 0.5f * (t[r][0] - t[r][1] + t[r][2]);
        float u3 = t[r][2];
        dst[((r * 4 + 0) * COUT + oc) * 64 + ic] = __float2half_rn(u0);
        dst[((r * 4 + 1) * COUT + oc) * 64 + ic] = __float2half_rn(u1);
        dst[((r * 4 + 2) * COUT + oc) * 64 + ic] = __float2half_rn(u2);
        dst[((r * 4 + 3) * COUT + oc) * 64 + ic] = __float2half_rn(u3);
    }
}

// ---------------- main kernel ----------------------------------------------
#define XSTG   0                       // x stage: 4 rows x 128 pix x 80B(pad)
                                       // (re-used as U bufs 2,3 after V done)
#define VS     40960                   // V: 16 pos x 64 tiles x 144B(pad)
#define VPOS_B 9216
#define US     188416                  // U bufs 0,1 (128 oc x 144B each)
#define UT_B   18432
#define SMEM_SZ 225280

static __device__ __forceinline__ unsigned smem_u32(const void* p) {
    unsigned r;
    asm("{ .reg .u64 t; cvta.to.shared.u64 t, %1; cvt.u32.u64 %0, t; }"
        : "=r"(r) : "l"(p));
    return r;
}
__device__ __forceinline__ void cp16(unsigned dst, const void* src, int bytes) {
    asm volatile("cp.async.cg.shared.global [%0], [%1], 16, %2;"
                 :: "r"(dst), "l"(src), "r"(bytes));
}
__device__ __forceinline__ void cp_commit() {
    asm volatile("cp.async.commit_group;");
}
__device__ __forceinline__ void ldsm4(unsigned r[4], unsigned addr) {
    asm volatile("ldmatrix.sync.aligned.m8n8.x4.shared.b16 {%0,%1,%2,%3}, [%4];"
                 : "=r"(r[0]), "=r"(r[1]), "=r"(r[2]), "=r"(r[3]) : "r"(addr));
}
__device__ __forceinline__ void mma16816(float c[4], const unsigned a[4],
                                         unsigned b0, unsigned b1) {
    asm volatile(
        "mma.sync.aligned.m16n8k16.row.col.f32.f16.f16.f32 "
        "{%0,%1,%2,%3}, {%4,%5,%6,%7}, {%8,%9}, {%0,%1,%2,%3};"
        : "+f"(c[0]), "+f"(c[1]), "+f"(c[2]), "+f"(c[3])
        : "r"(a[0]), "r"(a[1]), "r"(a[2]), "r"(a[3]), "r"(b0), "r"(b1));
}
__device__ __forceinline__ float gelu_tanh(float y) {
    float u = 1.5957691216f * (y + 0.044715f * y * y * y);
    return __fdividef(y, 1.0f + __expf(-u));
}

extern __shared__ char dyn_smem[];

__global__ __launch_bounds__(256, 1)
void convt_wino_kernel(const float* __restrict__ bias,
                       const float* __restrict__ gnw,
                       const float* __restrict__ gnb,
                       float* __restrict__ out) {
    const int hb = blockIdx.x;          // output rows {2hb, 2hb+1}
    const int n = blockIdx.y;
    const int tid = threadIdx.x;
    const int wid = tid >> 5;
    const int l = tid & 31;

    const unsigned sb = smem_u32(dyn_smem);

    auto ubuf = [&](int s) -> unsigned {
        return sb + ((s < 2) ? (US + (unsigned)s * UT_B)
                             : (XSTG + (unsigned)(s - 2) * UT_B));
    };

    // ---- async load helpers ----
    auto issue_x = [&](int half) {
#pragma unroll
        for (int k = 0; k < 8; k++) {
            int idx = tid + k * 256;        // 0..2047
            int c = idx & 3, pix = (idx >> 2) & 127, i = idx >> 9;
            int gh = 2 * hb - 2 + i;
            const char* src = (const char*)g_x1 +
                (size_t)(n * HH + (gh < 0 ? 0 : gh)) * 16384 +
                pix * 128 + half * 64 + c * 16;
            cp16(sb + XSTG + (unsigned)(i * 128 + pix) * 80 + c * 16, src,
                 (gh >= 0) ? 16 : 0);
        }
        cp_commit();
    };
    auto issue_u = [&](int pos, int buf) {
#pragma unroll
        for (int k = 0; k < 4; k++) {
            int idx = tid + k * 256;        // 0..1023
            int c = idx & 7, oc = idx >> 3;
            cp16(ubuf(buf) + (unsigned)oc * 144 + c * 16,
                 (const char*)g_u + (size_t)pos * 16384 + oc * 128 + c * 16, 16);
        }
        cp_commit();
    };

    // ---- V transform for one ic-half (fp32 math, fp16 store) ----
    auto transform_half = [&](int half) {
#pragma unroll
        for (int jb = 0; jb < 4; jb++) {
            int idx = tid + jb * 256;       // 0..1023
            int t = idx >> 4, q = idx & 15; // q = ic-pair within half
            float2 d[4][4];
#pragma unroll
            for (int i = 0; i < 4; i++)
#pragma unroll
                for (int jj = 0; jj < 4; jj++) {
                    int pix = 2 * t - 2 + jj;
                    if (pix >= 0) {
                        __half2 hv = *(const __half2*)
                            (dyn_smem + (i * 128 + pix) * 80 + q * 4);
                        d[i][jj] = __half22float2(hv);
                    } else d[i][jj] = make_float2(0.f, 0.f);
                }
            float2 e[4][4];
#pragma unroll
            for (int jj = 0; jj < 4; jj++) {
                e[0][jj] = make_float2(d[0][jj].x - d[2][jj].x, d[0][jj].y - d[2][jj].y);
                e[1][jj] = make_float2(d[1][jj].x + d[2][jj].x, d[1][jj].y + d[2][jj].y);
                e[2][jj] = make_float2(d[2][jj].x - d[1][jj].x, d[2][jj].y - d[1][jj].y);
                e[3][jj] = make_float2(d[1][jj].x - d[3][jj].x, d[1][jj].y - d[3][jj].y);
            }
#pragma unroll
            for (int r = 0; r < 4; r++) {
                float2 v[4];
                v[0] = make_float2(e[r][0].x - e[r][2].x, e[r][0].y - e[r][2].y);
                v[1] = make_float2(e[r][1].x + e[r][2].x, e[r][1].y + e[r][2].y);
                v[2] = make_float2(e[r][2].x - e[r][1].x, e[r][2].y - e[r][1].y);
                v[3] = make_float2(e[r][1].x - e[r][3].x, e[r][1].y - e[r][3].y);
#pragma unroll
                for (int s = 0; s < 4; s++)
                    *(__half2*)(dyn_smem + VS + (r * 4 + s) * VPOS_B +
                                t * 144 + half * 64 + q * 4) =
                        __floats2half2_rn(v[s].x, v[s].y);
            }
        }
    };

    // ---- prologue ----
    issue_x(0);                                  // g0
    issue_u(0, 0);                               // g1
    issue_u(1, 1);                               // g2
    asm volatile("cp.async.wait_group 2;");      // g0 (xh0) done
    __syncthreads();
    transform_half(0);
    __syncthreads();                             // x-stage half0 reads done
    issue_x(1);                                  // g3
    asm volatile("cp.async.wait_group 0;");      // all done (xh1, U0, U1)
    __syncthreads();
    transform_half(1);
    __syncthreads();                             // V complete, x stage free
    issue_u(2, 2);                               // g4 (into old x stage)

    // ---- per-lane ldmatrix components ----
    const unsigned aRowK = (unsigned)((l & 15) * 144 + ((l >> 4) & 1) * 16);
    const int bRow = (l & 7) + ((l & 16) ? 8 : 0);
    const unsigned bKoff = (l & 8) ? 16u : 0u;

    // ---- Y accumulators: [patch pi][tn][creg][a*2+b] ----
    float Y[4][2][4][4];
#pragma unroll
    for (int pi = 0; pi < 4; pi++)
#pragma unroll
        for (int tn = 0; tn < 2; tn++)
#pragma unroll
            for (int c = 0; c < 4; c++)
#pragma unroll
                for (int ab = 0; ab < 4; ab++) Y[pi][tn][c][ab] = 0.f;

    constexpr float AR[2][4] = {{1.f, 1.f, 1.f, 0.f}, {0.f, 1.f, -1.f, -1.f}};

    // ---- mainloop over 16 Winograd positions (3-deep U pipeline) ----
#pragma unroll
    for (int p = 0; p < 16; p++) {
        asm volatile("cp.async.wait_group 2;");   // U[p] resident
        __syncthreads();                           // all warps done with U[p-1]
        if (p + 3 < 16) issue_u(p + 3, (p + 3) & 3);

        const int pr = p >> 2, pc = p & 3;
        const unsigned ub = ubuf(p & 3) + (unsigned)(wid * 16) * 144;
        unsigned af[4][4];
#pragma unroll
        for (int kc = 0; kc < 4; kc++) ldsm4(af[kc], ub + aRowK + kc * 32);

#pragma unroll
        for (int g2 = 0; g2 < 2; g2++) {
            // 4 independent accumulation chains: (pi2, tn)
            float tmp[2][2][4];
#pragma unroll
            for (int pi2 = 0; pi2 < 2; pi2++)
#pragma unroll
                for (int tn = 0; tn < 2; tn++)
#pragma unroll
                    for (int c = 0; c < 4; c++) tmp[pi2][tn][c] = 0.f;

            const unsigned vb0 = sb + VS + (unsigned)p * VPOS_B +
                (unsigned)(((g2 * 2) * 16 + bRow) * 144) + bKoff;
            const unsigned vb1 = vb0 + 16 * 144;

#pragma unroll
            for (int kc = 0; kc < 4; kc++) {
                unsigned b0[4], b1[4];
                ldsm4(b0, vb0 + kc * 32);
                ldsm4(b1, vb1 + kc * 32);
                mma16816(tmp[0][0], af[kc], b0[0], b0[1]);
                mma16816(tmp[0][1], af[kc], b0[2], b0[3]);
                mma16816(tmp[1][0], af[kc], b1[0], b1[1]);
                mma16816(tmp[1][1], af[kc], b1[2], b1[3]);
            }
            // fold inverse transform (coefs 0/+-1, compile-time)
#pragma unroll
            for (int pi2 = 0; pi2 < 2; pi2++)
#pragma unroll
                for (int tn = 0; tn < 2; tn++)
#pragma unroll
                    for (int c = 0; c < 4; c++) {
                        float m = tmp[pi2][tn][c];
#pragma unroll
                        for (int a = 0; a < 2; a++) {
                            if (AR[a][pr] == 0.f) continue;
#pragma unroll
                            for (int b = 0; b < 2; b++) {
                                if (AR[b][pc] == 0.f) continue;
                                Y[g2 * 2 + pi2][tn][c][a * 2 + b] +=
                                    AR[a][pr] * AR[b][pc] * m;
                            }
                        }
                    }
        }
    }

    // ---------------- epilogue: bias + GELU + per-pixel GN + store ----------
    const int ocr = wid * 16 + (l >> 2);            // cregs 0,1; +8 for 2,3
    const float b_lo = __ldg(bias + ocr), b_hi = __ldg(bias + ocr + 8);
    const float w_lo = __ldg(gnw + ocr),  w_hi = __ldg(gnw + ocr + 8);
    const float a_lo = __ldg(gnb + ocr),  a_hi = __ldg(gnb + ocr + 8);

#pragma unroll
    for (int pi = 0; pi < 4; pi++) {
#pragma unroll
        for (int tn = 0; tn < 2; tn++) {
            float g[4][4], o[4][4];
#pragma unroll
            for (int ab = 0; ab < 4; ab++) {
                g[0][ab] = gelu_tanh(Y[pi][tn][0][ab] + b_lo);
                g[1][ab] = gelu_tanh(Y[pi][tn][1][ab] + b_lo);
                g[2][ab] = gelu_tanh(Y[pi][tn][2][ab] + b_hi);
                g[3][ab] = gelu_tanh(Y[pi][tn][3][ab] + b_hi);
            }
            // GN: group = this warp's 16 oc
#pragma unroll
            for (int u = 0; u < 2; u++)
#pragma unroll
                for (int ab = 0; ab < 4; ab++) {
                    float v0 = g[u][ab], v1 = g[u + 2][ab];
                    float s1 = v0 + v1, s2 = v0 * v0 + v1 * v1;
#pragma unroll
                    for (int m = 4; m <= 16; m <<= 1) {
                        s1 += __shfl_xor_sync(0xffffffffu, s1, m);
                        s2 += __shfl_xor_sync(0xffffffffu, s2, m);
                    }
                    float mean = s1 * (1.0f / 16.0f);
                    float var  = s2 * (1.0f / 16.0f) - mean * mean;
                    float rstd = rsqrtf(var + 1e-5f);
                    o[u][ab]     = (v0 - mean) * rstd * w_lo + a_lo;
                    o[u + 2][ab] = (v1 - mean) * rstd * w_hi + a_hi;
                }
            int colbase = 32 * pi + 16 * tn + 4 * (l & 3);
#pragma unroll
            for (int rr = 0; rr < 2; rr++) {
                int oc = ocr + rr * 8;
#pragma unroll
                for (int a = 0; a < 2; a++) {
                    float* dst = out + (((size_t)n * COUT + oc) * HH +
                                        (2 * hb + a)) * WW + colbase;
                    *(float4*)dst = make_float4(o[rr * 2 + 0][a * 2 + 0],
                                                o[rr * 2 + 0][a * 2 + 1],
                                                o[rr * 2 + 1][a * 2 + 0],
                                                o[rr * 2 + 1][a * 2 + 1]);
                }
            }
        }
    }
}

extern "C" void kernel_launch(void* const* d_in, const int* in_sizes, int n_in,
                              void* d_out, int out_size) {
    const float* x   = (const float*)d_in[0];
    const float* w   = (const float*)d_in[1];
    const float* b   = (const float*)d_in[2];
    const float* gnw = (const float*)d_in[3];
    const float* gnb = (const float*)d_in[4];
    float* out = (float*)d_out;

    prep_uw<<<32, 256>>>(w);
    prep_x<<<dim3(HH, NB), 256>>>(x);

    cudaFuncSetAttribute(convt_wino_kernel,
                         cudaFuncAttributeMaxDynamicSharedMemorySize, SMEM_SZ);
    convt_wino_kernel<<<dim3(HH / 2, NB), 256, SMEM_SZ>>>(b, gnw, gnb, out);
}

// round 12
// speedup vs baseline: 1.1193x; 1.1193x over previous
#include <cuda_runtime.h>
#include <cuda_fp16.h>
#include <math.h>
#include <stdint.h>

#define CIN   64
#define COUT  128
#define HH    128
#define WW    128
#define NB    32

// ---------------- persistent scratch (__device__ globals) -------------------
// Activations: [n][h][pix(128)][ic(64)] fp16 (16KB per row tile)
__device__ uint4 g_x1[(size_t)NB * HH * 1024];
// Winograd-transformed weights: [pos(16)][oc(128)][ic(64)] fp16 (16KB per pos)
__device__ uint4 g_u[16 * 1024];

// ---------------- pre-pass: x -> fp16 transposed tiles ----------------------
__global__ void prep_x(const float* __restrict__ x) {
    __shared__ __half sh[128 * 72];
    const int h = blockIdx.x, n = blockIdx.y;
    const float* xb = x + (size_t)n * CIN * HH * WW;
#pragma unroll
    for (int i = 0; i < 8; i++) {
        int f = threadIdx.x + i * 256;      // 0..2047 = ic*32 + p4
        int ic = f >> 5, p4 = f & 31;
        float4 v = *(const float4*)(xb + ((size_t)ic * HH + h) * WW + p4 * 4);
        float vv[4] = {v.x, v.y, v.z, v.w};
#pragma unroll
        for (int j = 0; j < 4; j++)
            sh[(p4 * 4 + j) * 72 + ic] = __float2half_rn(vv[j]);
    }
    __syncthreads();
    uint4* dst = g_x1 + (size_t)(n * HH + h) * 1024;
    for (int q = threadIdx.x; q < 1024; q += 256) {
        int p = q >> 3, c = q & 7;
        dst[q] = *(const uint4*)((const char*)sh + p * 144 + c * 16);
    }
}

// ---------------- pre-pass: weights -> Winograd U (fp32-exact -> fp16) ------
__global__ void prep_uw(const float* __restrict__ w) {
    int idx = blockIdx.x * 256 + threadIdx.x;      // 0..8191 = oc*64+ic
    if (idx >= COUT * CIN) return;
    int oc = idx >> 6, ic = idx & 63;
    float g[3][3];
#pragma unroll
    for (int r = 0; r < 3; r++)
#pragma unroll
        for (int c = 0; c < 3; c++)
            g[r][c] = w[((size_t)(ic * COUT + oc) * 3 + (2 - r)) * 3 + (2 - c)];
    float t[4][3];
#pragma unroll
    for (int c = 0; c < 3; c++) {
        t[0][c] = g[0][c];
        t[1][c] = 0.5f * (g[0][c] + g[1][c] + g[2][c]);
        t[2][c] = 0.5f * (g[0][c] - g[1][c] + g[2][c]);
        t[3][c] = g[2][c];
    }
    __half* dst = (__half*)g_u;
#pragma unroll
    for (int r = 0; r < 4; r++) {
        float u0 = t[r][0];
        float u1 = 0.5f * (t[r][0] + t[r][1] + t[r][2]);
        float u2 = 0.5f * (t[r][0] - t[r][1] + t[r][2]);
        float u3 = t[r][2];
        dst[((r * 4 + 0) * COUT + oc) * 64 + ic] = __float2half_rn(u0);
        dst[((r * 4 + 1) * COUT + oc) * 64 + ic] = __float2half_rn(u1);
        dst[((r * 4 + 2) * COUT + oc) * 64 + ic] = __float2half_rn(u2);
        dst[((r * 4 + 3) * COUT + oc) * 64 + ic] = __float2half_rn(u3);
    }
}

// ---------------- main kernel ----------------------------------------------
// CTA = output rows {2hb, 2hb+1} x 64 pixels (32 Winograd tiles).
// smem: V [16 pos][32 tiles][144B]  = 73728
//       UX region (36864): 2 U bufs [128 oc][144B] = 18432 each;
//       x stage [4 rows][68 lp][128B] = 34816 aliased here pre-mainloop.
#define VPOS_B 4608
#define UX     73728
#define UT_B   18432
#define SMEM_SZ 110592

static __device__ __forceinline__ unsigned smem_u32(const void* p) {
    unsigned r;
    asm("{ .reg .u64 t; cvta.to.shared.u64 t, %1; cvt.u32.u64 %0, t; }"
        : "=r"(r) : "l"(p));
    return r;
}
__device__ __forceinline__ void cp16(unsigned dst, const void* src, int bytes) {
    asm volatile("cp.async.cg.shared.global [%0], [%1], 16, %2;"
                 :: "r"(dst), "l"(src), "r"(bytes));
}
__device__ __forceinline__ void cp_commit() {
    asm volatile("cp.async.commit_group;");
}
__device__ __forceinline__ void ldsm4(unsigned r[4], unsigned addr) {
    asm volatile("ldmatrix.sync.aligned.m8n8.x4.shared.b16 {%0,%1,%2,%3}, [%4];"
                 : "=r"(r[0]), "=r"(r[1]), "=r"(r[2]), "=r"(r[3]) : "r"(addr));
}
__device__ __forceinline__ void mma16816(float c[4], const unsigned a[4],
                                         unsigned b0, unsigned b1) {
    asm volatile(
        "mma.sync.aligned.m16n8k16.row.col.f32.f16.f16.f32 "
        "{%0,%1,%2,%3}, {%4,%5,%6,%7}, {%8,%9}, {%0,%1,%2,%3};"
        : "+f"(c[0]), "+f"(c[1]), "+f"(c[2]), "+f"(c[3])
        : "r"(a[0]), "r"(a[1]), "r"(a[2]), "r"(a[3]), "r"(b0), "r"(b1));
}
__device__ __forceinline__ float gelu_tanh(float y) {
    float u = 1.5957691216f * (y + 0.044715f * y * y * y);
    return __fdividef(y, 1.0f + __expf(-u));
}

extern __shared__ char dyn_smem[];

__global__ __launch_bounds__(256, 2)
void convt_wino_kernel(const float* __restrict__ bias,
                       const float* __restrict__ gnw,
                       const float* __restrict__ gnb,
                       float* __restrict__ out) {
    const int hb = blockIdx.x >> 1;     // output rows {2hb, 2hb+1}
    const int ps = blockIdx.x & 1;      // pixel slice: 64 px at ps*64
    const int n = blockIdx.y;
    const int tid = threadIdx.x;
    const int wid = tid >> 5;
    const int l = tid & 31;

    const unsigned sb = smem_u32(dyn_smem);

    // ---- prologue: x stage (4 rows x 66 valid lp x 64 ic) into UX region ----
    // lp = global pixel - (ps*64 - 2); lp in [0,68) loaded, [0,66) used.
    {
#pragma unroll
        for (int k = 0; k < 9; k++) {
            int idx = tid + k * 256;            // 0..2303; need < 2176
            if (idx < 4 * 68 * 8) {
                int c = idx & 7;
                int lp = (idx >> 3) % 68;
                int i = idx / (68 * 8);
                int gh = 2 * hb - 2 + i;
                int gp = ps * 64 - 2 + lp;
                bool ok = (gh >= 0) && (gp >= 0) && (gp < WW);
                const char* src = (const char*)g_x1 +
                    (size_t)(n * HH + (gh < 0 ? 0 : gh)) * 16384 +
                    (ok ? gp : 0) * 128 + c * 16;
                cp16(sb + UX + (unsigned)(i * 68 + lp) * 128 + c * 16, src,
                     ok ? 16 : 0);
            }
        }
        cp_commit();
        asm volatile("cp.async.wait_group 0;");
        __syncthreads();
    }

    // ---- V transform (fp32 math, fp16 store), 32 tiles x 32 ic-pairs -------
#pragma unroll
    for (int jb = 0; jb < 4; jb++) {
        int idx = tid + jb * 256;       // 0..1023
        int tl = idx >> 5, q = idx & 31;
        float2 d[4][4];
#pragma unroll
        for (int i = 0; i < 4; i++)
#pragma unroll
            for (int jj = 0; jj < 4; jj++) {
                __half2 hv = *(const __half2*)
                    (dyn_smem + UX + (i * 68 + 2 * tl + jj) * 128 + q * 4);
                d[i][jj] = __half22float2(hv);
            }
        float2 e[4][4];
#pragma unroll
        for (int jj = 0; jj < 4; jj++) {
            e[0][jj] = make_float2(d[0][jj].x - d[2][jj].x, d[0][jj].y - d[2][jj].y);
            e[1][jj] = make_float2(d[1][jj].x + d[2][jj].x, d[1][jj].y + d[2][jj].y);
            e[2][jj] = make_float2(d[2][jj].x - d[1][jj].x, d[2][jj].y - d[1][jj].y);
            e[3][jj] = make_float2(d[1][jj].x - d[3][jj].x, d[1][jj].y - d[3][jj].y);
        }
#pragma unroll
        for (int r = 0; r < 4; r++) {
            float2 v[4];
            v[0] = make_float2(e[r][0].x - e[r][2].x, e[r][0].y - e[r][2].y);
            v[1] = make_float2(e[r][1].x + e[r][2].x, e[r][1].y + e[r][2].y);
            v[2] = make_float2(e[r][2].x - e[r][1].x, e[r][2].y - e[r][1].y);
            v[3] = make_float2(e[r][1].x - e[r][3].x, e[r][1].y - e[r][3].y);
#pragma unroll
            for (int s = 0; s < 4; s++)
                *(__half2*)(dyn_smem + (r * 4 + s) * VPOS_B + tl * 144 + q * 4) =
                    __floats2half2_rn(v[s].x, v[s].y);
        }
    }
    __syncthreads();                    // x-stage reads done; V stored

    // ---- U loads (into UX region, x stage now dead) ----
    auto issue_u = [&](int pos, int buf) {
#pragma unroll
        for (int k = 0; k < 4; k++) {
            int idx = tid + k * 256;        // 0..1023
            int c = idx & 7, oc = idx >> 3;
            cp16(sb + UX + (unsigned)buf * UT_B + (unsigned)oc * 144 + c * 16,
                 (const char*)g_u + (size_t)pos * 16384 + oc * 128 + c * 16, 16);
        }
        cp_commit();
    };
    issue_u(0, 0);

    // ---- per-lane ldmatrix components ----
    const unsigned aRowK = (unsigned)((l & 15) * 144 + ((l >> 4) & 1) * 16);
    const int bRow = (l & 7) + ((l & 16) ? 8 : 0);
    const unsigned bKoff = (l & 8) ? 16u : 0u;

    // ---- Y accumulators: [group pi][tn][creg][a*2+b] = 64 regs ----
    float Y[2][2][4][4];
#pragma unroll
    for (int pi = 0; pi < 2; pi++)
#pragma unroll
        for (int tn = 0; tn < 2; tn++)
#pragma unroll
            for (int c = 0; c < 4; c++)
#pragma unroll
                for (int ab = 0; ab < 4; ab++) Y[pi][tn][c][ab] = 0.f;

    constexpr float AR[2][4] = {{1.f, 1.f, 1.f, 0.f}, {0.f, 1.f, -1.f, -1.f}};

    // ---- mainloop over 16 Winograd positions (2-buf, depth-1 overlap) ----
#pragma unroll
    for (int p = 0; p < 16; p++) {
        asm volatile("cp.async.wait_group 0;");   // U[p] landed (this thread)
        __syncthreads();                           // all threads' U[p] visible;
                                                   // all done reading U[p-1]
        if (p + 1 < 16) issue_u(p + 1, (p + 1) & 1);

        const int pr = p >> 2, pc = p & 3;
        const unsigned ub = sb + UX + (unsigned)(p & 1) * UT_B +
                            (unsigned)(wid * 16) * 144;
        const unsigned vb0 = sb + (unsigned)p * VPOS_B +
                             (unsigned)(bRow * 144) + bKoff;
        const unsigned vb1 = vb0 + 16 * 144;

        float tmp[2][2][4];
#pragma unroll
        for (int pi = 0; pi < 2; pi++)
#pragma unroll
            for (int tn = 0; tn < 2; tn++)
#pragma unroll
                for (int c = 0; c < 4; c++) tmp[pi][tn][c] = 0.f;

#pragma unroll
        for (int kc = 0; kc < 4; kc++) {
            unsigned af[4], b0[4], b1[4];
            ldsm4(af, ub + aRowK + kc * 32);
            ldsm4(b0, vb0 + kc * 32);
            ldsm4(b1, vb1 + kc * 32);
            mma16816(tmp[0][0], af, b0[0], b0[1]);
            mma16816(tmp[0][1], af, b0[2], b0[3]);
            mma16816(tmp[1][0], af, b1[0], b1[1]);
            mma16816(tmp[1][1], af, b1[2], b1[3]);
        }
        // fold inverse transform (coefs 0/+-1, compile-time)
#pragma unroll
        for (int pi = 0; pi < 2; pi++)
#pragma unroll
            for (int tn = 0; tn < 2; tn++)
#pragma unroll
                for (int c = 0; c < 4; c++) {
                    float m = tmp[pi][tn][c];
#pragma unroll
                    for (int a = 0; a < 2; a++) {
                        if (AR[a][pr] == 0.f) continue;
#pragma unroll
                        for (int b = 0; b < 2; b++) {
                            if (AR[b][pc] == 0.f) continue;
                            Y[pi][tn][c][a * 2 + b] +=
                                AR[a][pr] * AR[b][pc] * m;
                        }
                    }
                }
    }

    // ---------------- epilogue: bias + GELU + per-pixel GN + store ----------
    const int ocr = wid * 16 + (l >> 2);            // cregs 0,1; +8 for 2,3
    const float b_lo = __ldg(bias + ocr), b_hi = __ldg(bias + ocr + 8);
    const float w_lo = __ldg(gnw + ocr),  w_hi = __ldg(gnw + ocr + 8);
    const float a_lo = __ldg(gnb + ocr),  a_hi = __ldg(gnb + ocr + 8);

#pragma unroll
    for (int pi = 0; pi < 2; pi++) {
#pragma unroll
        for (int tn = 0; tn < 2; tn++) {
            float g[4][4], o[4][4];
#pragma unroll
            for (int ab = 0; ab < 4; ab++) {
                g[0][ab] = gelu_tanh(Y[pi][tn][0][ab] + b_lo);
                g[1][ab] = gelu_tanh(Y[pi][tn][1][ab] + b_lo);
                g[2][ab] = gelu_tanh(Y[pi][tn][2][ab] + b_hi);
                g[3][ab] = gelu_tanh(Y[pi][tn][3][ab] + b_hi);
            }
            // GN: group = this warp's 16 oc (lanes l^4, l^8, l^16 + creg pair)
#pragma unroll
            for (int u = 0; u < 2; u++)
#pragma unroll
                for (int ab = 0; ab < 4; ab++) {
                    float v0 = g[u][ab], v1 = g[u + 2][ab];
                    float s1 = v0 + v1, s2 = v0 * v0 + v1 * v1;
#pragma unroll
                    for (int m = 4; m <= 16; m <<= 1) {
                        s1 += __shfl_xor_sync(0xffffffffu, s1, m);
                        s2 += __shfl_xor_sync(0xffffffffu, s2, m);
                    }
                    float mean = s1 * (1.0f / 16.0f);
                    float var  = s2 * (1.0f / 16.0f) - mean * mean;
                    float rstd = rsqrtf(var + 1e-5f);
                    o[u][ab]     = (v0 - mean) * rstd * w_lo + a_lo;
                    o[u + 2][ab] = (v1 - mean) * rstd * w_hi + a_hi;
                }
            int colbase = ps * 64 + 32 * pi + 16 * tn + 4 * (l & 3);
#pragma unroll
            for (int rr = 0; rr < 2; rr++) {
                int oc = ocr + rr * 8;
#pragma unroll
                for (int a = 0; a < 2; a++) {
                    float* dst = out + (((size_t)n * COUT + oc) * HH +
                                        (2 * hb + a)) * WW + colbase;
                    *(float4*)dst = make_float4(o[rr * 2 + 0][a * 2 + 0],
                                                o[rr * 2 + 0][a * 2 + 1],
                                                o[rr * 2 + 1][a * 2 + 0],
                                                o[rr * 2 + 1][a * 2 + 1]);
                }
            }
        }
    }
}

extern "C" void kernel_launch(void* const* d_in, const int* in_sizes, int n_in,
                              void* d_out, int out_size) {
    const float* x   = (const float*)d_in[0];
    const float* w   = (const float*)d_in[1];
    const float* b   = (const float*)d_in[2];
    const float* gnw = (const float*)d_in[3];
    const float* gnb = (const float*)d_in[4];
    float* out = (float*)d_out;

    prep_uw<<<32, 256>>>(w);
    prep_x<<<dim3(HH, NB), 256>>>(x);

    cudaFuncSetAttribute(convt_wino_kernel,
                         cudaFuncAttributeMaxDynamicSharedMemorySize, SMEM_SZ);
    convt_wino_kernel<<<dim3(HH, NB), 256, SMEM_SZ>>>(b, gnw, gnb, out);
}

// round 13
// speedup vs baseline: 1.1837x; 1.0575x over previous
#include <cuda_runtime.h>
#include <cuda_fp16.h>
#include <math.h>
#include <stdint.h>

#define CIN   64
#define COUT  128
#define HH    128
#define WW    128
#define NB    32

// ---------------- persistent scratch (__device__ globals) -------------------
// Activations: [n][h][pix(128)][ic(64)] fp16 (16KB per row tile)
__device__ uint4 g_x1[(size_t)NB * HH * 1024];
// Winograd-transformed weights: [pos(16)][oc(128)][ic(64)] fp16 (16KB per pos)
__device__ uint4 g_u[16 * 1024];

// ---------------- pre-pass: x -> fp16 transposed tiles ----------------------
__global__ void prep_x(const float* __restrict__ x) {
    __shared__ __half sh[128 * 72];
    const int h = blockIdx.x, n = blockIdx.y;
    const float* xb = x + (size_t)n * CIN * HH * WW;
#pragma unroll
    for (int i = 0; i < 8; i++) {
        int f = threadIdx.x + i * 256;      // 0..2047 = ic*32 + p4
        int ic = f >> 5, p4 = f & 31;
        float4 v = *(const float4*)(xb + ((size_t)ic * HH + h) * WW + p4 * 4);
        float vv[4] = {v.x, v.y, v.z, v.w};
#pragma unroll
        for (int j = 0; j < 4; j++)
            sh[(p4 * 4 + j) * 72 + ic] = __float2half_rn(vv[j]);
    }
    __syncthreads();
    uint4* dst = g_x1 + (size_t)(n * HH + h) * 1024;
    for (int q = threadIdx.x; q < 1024; q += 256) {
        int p = q >> 3, c = q & 7;
        dst[q] = *(const uint4*)((const char*)sh + p * 144 + c * 16);
    }
}

// ---------------- pre-pass: weights -> Winograd U (fp32-exact -> fp16) ------
__global__ void prep_uw(const float* __restrict__ w) {
    int idx = blockIdx.x * 256 + threadIdx.x;      // 0..8191 = oc*64+ic
    if (idx >= COUT * CIN) return;
    int oc = idx >> 6, ic = idx & 63;
    float g[3][3];
#pragma unroll
    for (int r = 0; r < 3; r++)
#pragma unroll
        for (int c = 0; c < 3; c++)
            g[r][c] = w[((size_t)(ic * COUT + oc) * 3 + (2 - r)) * 3 + (2 - c)];
    float t[4][3];
#pragma unroll
    for (int c = 0; c < 3; c++) {
        t[0][c] = g[0][c];
        t[1][c] = 0.5f * (g[0][c] + g[1][c] + g[2][c]);
        t[2][c] = 0.5f * (g[0][c] - g[1][c] + g[2][c]);
        t[3][c] = g[2][c];
    }
    __half* dst = (__half*)g_u;
#pragma unroll
    for (int r = 0; r < 4; r++) {
        float u0 = t[r][0];
        float u1 = 0.5f * (t[r][0] + t[r][1] + t[r][2]);
        float u2 = 0.5f * (t[r][0] - t[r][1] + t[r][2]);
        float u3 = t[r][2];
        dst[((r * 4 + 0) * COUT + oc) * 64 + ic] = __float2half_rn(u0);
        dst[((r * 4 + 1) * COUT + oc) * 64 + ic] = __float2half_rn(u1);
        dst[((r * 4 + 2) * COUT + oc) * 64 + ic] = __float2half_rn(u2);
        dst[((r * 4 + 3) * COUT + oc) * 64 + ic] = __float2half_rn(u3);
    }
}

// ---------------- main kernel ----------------------------------------------
// CTA = output rows {2hb, 2hb+1} x 64 pixels (32 Winograd tiles).
// smem (XOR-swizzled 128B rows, no padding):
//   V  [16 pos][32 tiles][128B]          = 65536
//   U  3 bufs  [128 oc][128B]            = 49152  (x stage 34816B aliased pre-loop)
#define VPOS_B 4096
#define US     65536
#define UT_B   16384
#define SMEM_SZ 114688

static __device__ __forceinline__ unsigned smem_u32(const void* p) {
    unsigned r;
    asm("{ .reg .u64 t; cvta.to.shared.u64 t, %1; cvt.u32.u64 %0, t; }"
        : "=r"(r) : "l"(p));
    return r;
}
__device__ __forceinline__ void cp16(unsigned dst, const void* src, int bytes) {
    asm volatile("cp.async.cg.shared.global [%0], [%1], 16, %2;"
                 :: "r"(dst), "l"(src), "r"(bytes));
}
__device__ __forceinline__ void cp_commit() {
    asm volatile("cp.async.commit_group;");
}
__device__ __forceinline__ void ldsm4(unsigned r[4], unsigned addr) {
    asm volatile("ldmatrix.sync.aligned.m8n8.x4.shared.b16 {%0,%1,%2,%3}, [%4];"
                 : "=r"(r[0]), "=r"(r[1]), "=r"(r[2]), "=r"(r[3]) : "r"(addr));
}
__device__ __forceinline__ void mma16816(float c[4], const unsigned a[4],
                                         unsigned b0, unsigned b1) {
    asm volatile(
        "mma.sync.aligned.m16n8k16.row.col.f32.f16.f16.f32 "
        "{%0,%1,%2,%3}, {%4,%5,%6,%7}, {%8,%9}, {%0,%1,%2,%3};"
        : "+f"(c[0]), "+f"(c[1]), "+f"(c[2]), "+f"(c[3])
        : "r"(a[0]), "r"(a[1]), "r"(a[2]), "r"(a[3]), "r"(b0), "r"(b1));
}
__device__ __forceinline__ float gelu_tanh(float y) {
    float u = 1.5957691216f * (y + 0.044715f * y * y * y);
    return __fdividef(y, 1.0f + __expf(-u));
}

extern __shared__ char dyn_smem[];

__global__ __launch_bounds__(256, 2)
void convt_wino_kernel(const float* __restrict__ bias,
                       const float* __restrict__ gnw,
                       const float* __restrict__ gnb,
                       float* __restrict__ out) {
    const int hb = blockIdx.x >> 1;     // output rows {2hb, 2hb+1}
    const int ps = blockIdx.x & 1;      // pixel slice: 64 px at ps*64
    const int n = blockIdx.y;
    const int tid = threadIdx.x;
    const int wid = tid >> 5;
    const int l = tid & 31;

    const unsigned sb = smem_u32(dyn_smem);

    // ---- prologue: x stage (4 rows x 68 lp x 64 ic) into U region ----------
    {
#pragma unroll
        for (int k = 0; k < 9; k++) {
            int idx = tid + k * 256;            // need < 2176
            if (idx < 4 * 68 * 8) {
                int c = idx & 7;
                int lp = (idx >> 3) % 68;
                int i = idx / (68 * 8);
                int gh = 2 * hb - 2 + i;
                int gp = ps * 64 - 2 + lp;
                bool ok = (gh >= 0) && (gp >= 0) && (gp < WW);
                const char* src = (const char*)g_x1 +
                    (size_t)(n * HH + (gh < 0 ? 0 : gh)) * 16384 +
                    (ok ? gp : 0) * 128 + c * 16;
                cp16(sb + US + (unsigned)(i * 68 + lp) * 128 + c * 16, src,
                     ok ? 16 : 0);
            }
        }
        cp_commit();
        asm volatile("cp.async.wait_group 0;");
        __syncthreads();
    }

    // ---- V transform (fp32 math, fp16 store, swizzled rows) ----------------
#pragma unroll
    for (int jb = 0; jb < 4; jb++) {
        int idx = tid + jb * 256;       // 0..1023
        int tl = idx >> 5, q = idx & 31;
        const unsigned vxr = (unsigned)((tl & 7) << 4);
        float2 d[4][4];
#pragma unroll
        for (int i = 0; i < 4; i++)
#pragma unroll
            for (int jj = 0; jj < 4; jj++) {
                __half2 hv = *(const __half2*)
                    (dyn_smem + US + (i * 68 + 2 * tl + jj) * 128 + q * 4);
                d[i][jj] = __half22float2(hv);
            }
        float2 e[4][4];
#pragma unroll
        for (int jj = 0; jj < 4; jj++) {
            e[0][jj] = make_float2(d[0][jj].x - d[2][jj].x, d[0][jj].y - d[2][jj].y);
            e[1][jj] = make_float2(d[1][jj].x + d[2][jj].x, d[1][jj].y + d[2][jj].y);
            e[2][jj] = make_float2(d[2][jj].x - d[1][jj].x, d[2][jj].y - d[1][jj].y);
            e[3][jj] = make_float2(d[1][jj].x - d[3][jj].x, d[1][jj].y - d[3][jj].y);
        }
#pragma unroll
        for (int r = 0; r < 4; r++) {
            float2 v[4];
            v[0] = make_float2(e[r][0].x - e[r][2].x, e[r][0].y - e[r][2].y);
            v[1] = make_float2(e[r][1].x + e[r][2].x, e[r][1].y + e[r][2].y);
            v[2] = make_float2(e[r][2].x - e[r][1].x, e[r][2].y - e[r][1].y);
            v[3] = make_float2(e[r][1].x - e[r][3].x, e[r][1].y - e[r][3].y);
#pragma unroll
            for (int s = 0; s < 4; s++)
                *(__half2*)(dyn_smem + (r * 4 + s) * VPOS_B + tl * 128 +
                            (unsigned)((q * 4) ^ vxr)) =
                    __floats2half2_rn(v[s].x, v[s].y);
        }
    }
    __syncthreads();                    // x reads done; V visible to all warps.
                                        // LAST barrier in the kernel.

    // ---- per-warp U slice load: warp w loads only oc rows [w*16, w*16+16) --
    const int ur = l & 15;                          // row within slice
    const int uhf = l >> 4;                         // 64B half
    const unsigned uxr = (unsigned)((ur & 7) << 4);
    auto issue_u = [&](int pos, int buf) {
        unsigned drow = sb + US + (unsigned)buf * UT_B +
                        (unsigned)(wid * 16 + ur) * 128;
        const char* srow = (const char*)g_u + (size_t)pos * 16384 +
                           (wid * 16 + ur) * 128 + uhf * 64;
#pragma unroll
        for (int k2 = 0; k2 < 4; k2++)
            cp16(drow + (((unsigned)(uhf * 64 + k2 * 16)) ^ uxr),
                 srow + k2 * 16, 16);
        cp_commit();
    };
    issue_u(0, 0);
    issue_u(1, 1);
    issue_u(2, 2);

    // ---- per-lane ldmatrix components ----
    const unsigned aBase = (unsigned)(wid * 16 + (l & 15)) * 128;
    const unsigned aColB = (unsigned)((l >> 4) * 16);
    const unsigned aXr = (unsigned)((l & 7) << 4);
    const int bRow = (l & 7) + ((l & 16) ? 8 : 0);
    const unsigned bXr = (unsigned)((bRow & 7) << 4);
    const unsigned bKoff = (l & 8) ? 16u : 0u;

    // ---- Y accumulators ----
    float Y[2][2][4][4];
#pragma unroll
    for (int pi = 0; pi < 2; pi++)
#pragma unroll
        for (int tn = 0; tn < 2; tn++)
#pragma unroll
            for (int c = 0; c < 4; c++)
#pragma unroll
                for (int ab = 0; ab < 4; ab++) Y[pi][tn][c][ab] = 0.f;

    constexpr float AR[2][4] = {{1.f, 1.f, 1.f, 0.f}, {0.f, 1.f, -1.f, -1.f}};

    // ---- barrier-free mainloop over 16 Winograd positions ------------------
#pragma unroll
    for (int p = 0; p < 16; p++) {
        // per-warp: all but the 2 newest groups done => this warp's U[p] ready
        asm volatile("cp.async.wait_group 2;");

        const int pr = p >> 2, pc = p & 3;
        const unsigned ub = sb + US + (unsigned)(p % 3) * UT_B + aBase;
        const unsigned vb0 = sb + (unsigned)p * VPOS_B + (unsigned)bRow * 128;
        const unsigned vb1 = vb0 + 2048;

        float tmp[2][2][4];
#pragma unroll
        for (int pi = 0; pi < 2; pi++)
#pragma unroll
            for (int tn = 0; tn < 2; tn++)
#pragma unroll
                for (int c = 0; c < 4; c++) tmp[pi][tn][c] = 0.f;

#pragma unroll
        for (int kc = 0; kc < 4; kc++) {
            unsigned af[4], b0[4], b1[4];
            ldsm4(af, ub + (((unsigned)(kc * 32) + aColB) ^ aXr));
            const unsigned csw = ((unsigned)(kc * 32) + bKoff) ^ bXr;
            ldsm4(b0, vb0 + csw);
            ldsm4(b1, vb1 + csw);
            mma16816(tmp[0][0], af, b0[0], b0[1]);
            mma16816(tmp[0][1], af, b0[2], b0[3]);
            mma16816(tmp[1][0], af, b1[0], b1[1]);
            mma16816(tmp[1][1], af, b1[2], b1[3]);
        }

        // prefetch this warp's slice of U[p+3] (always commit to keep group
        // arithmetic uniform; empty groups are legal)
        if (p + 3 < 16) issue_u(p + 3, (p + 3) % 3);
        else cp_commit();

        // fold inverse transform (coefs 0/+-1, compile-time)
#pragma unroll
        for (int pi = 0; pi < 2; pi++)
#pragma unroll
            for (int tn = 0; tn < 2; tn++)
#pragma unroll
                for (int c = 0; c < 4; c++) {
                    float m = tmp[pi][tn][c];
#pragma unroll
                    for (int a = 0; a < 2; a++) {
                        if (AR[a][pr] == 0.f) continue;
#pragma unroll
                        for (int b = 0; b < 2; b++) {
                            if (AR[b][pc] == 0.f) continue;
                            Y[pi][tn][c][a * 2 + b] +=
                                AR[a][pr] * AR[b][pc] * m;
                        }
                    }
                }
    }

    // ---------------- epilogue: bias + GELU + per-pixel GN + store ----------
    const int ocr = wid * 16 + (l >> 2);
    const float b_lo = __ldg(bias + ocr), b_hi = __ldg(bias + ocr + 8);
    const float w_lo = __ldg(gnw + ocr),  w_hi = __ldg(gnw + ocr + 8);
    const float a_lo = __ldg(gnb + ocr),  a_hi = __ldg(gnb + ocr + 8);

#pragma unroll
    for (int pi = 0; pi < 2; pi++) {
#pragma unroll
        for (int tn = 0; tn < 2; tn++) {
            float g[4][4], o[4][4];
#pragma unroll
            for (int ab = 0; ab < 4; ab++) {
                g[0][ab] = gelu_tanh(Y[pi][tn][0][ab] + b_lo);
                g[1][ab] = gelu_tanh(Y[pi][tn][1][ab] + b_lo);
                g[2][ab] = gelu_tanh(Y[pi][tn][2][ab] + b_hi);
                g[3][ab] = gelu_tanh(Y[pi][tn][3][ab] + b_hi);
            }
#pragma unroll
            for (int u = 0; u < 2; u++)
#pragma unroll
                for (int ab = 0; ab < 4; ab++) {
                    float v0 = g[u][ab], v1 = g[u + 2][ab];
                    float s1 = v0 + v1, s2 = v0 * v0 + v1 * v1;
#pragma unroll
                    for (int m = 4; m <= 16; m <<= 1) {
                        s1 += __shfl_xor_sync(0xffffffffu, s1, m);
                        s2 += __shfl_xor_sync(0xffffffffu, s2, m);
                    }
                    float mean = s1 * (1.0f / 16.0f);
                    float var  = s2 * (1.0f / 16.0f) - mean * mean;
                    float rstd = rsqrtf(var + 1e-5f);
                    o[u][ab]     = (v0 - mean) * rstd * w_lo + a_lo;
                    o[u + 2][ab] = (v1 - mean) * rstd * w_hi + a_hi;
                }
            int colbase = ps * 64 + 32 * pi + 16 * tn + 4 * (l & 3);
#pragma unroll
            for (int rr = 0; rr < 2; rr++) {
                int oc = ocr + rr * 8;
#pragma unroll
                for (int a = 0; a < 2; a++) {
                    float* dst = out + (((size_t)n * COUT + oc) * HH +
                                        (2 * hb + a)) * WW + colbase;
                    *(float4*)dst = make_float4(o[rr * 2 + 0][a * 2 + 0],
                                                o[rr * 2 + 0][a * 2 + 1],
                                                o[rr * 2 + 1][a * 2 + 0],
                                                o[rr * 2 + 1][a * 2 + 1]);
                }
            }
        }
    }
}

extern "C" void kernel_launch(void* const* d_in, const int* in_sizes, int n_in,
                              void* d_out, int out_size) {
    const float* x   = (const float*)d_in[0];
    const float* w   = (const float*)d_in[1];
    const float* b   = (const float*)d_in[2];
    const float* gnw = (const float*)d_in[3];
    const float* gnb = (const float*)d_in[4];
    float* out = (float*)d_out;

    prep_uw<<<32, 256>>>(w);
    prep_x<<<dim3(HH, NB), 256>>>(x);

    cudaFuncSetAttribute(convt_wino_kernel,
                         cudaFuncAttributeMaxDynamicSharedMemorySize, SMEM_SZ);
    convt_wino_kernel<<<dim3(HH, NB), 256, SMEM_SZ>>>(b, gnw, gnb, out);
}